// round 15
// baseline (speedup 1.0000x reference)
#include <cuda_runtime.h>
#include <cuda_fp16.h>
#include <math.h>
#include <stdint.h>

// Problem constants
#define BQ   4
#define SEQ  2048
#define DM   1024
#define NH   16
#define DKH  64
#define MTOT (BQ*SEQ)   // 8192

// ---------------------------------------------------------------------------
// Scratch (device globals: allocation-free)
// fp16 mixed-precision scheme (calibrated: sigma ~1.9e-4 per rounding source):
//   X: hi+lo.  Q projection: 2-term (feeds exponentiated scores).
//   K/V projections: 1-term (outputs rounded to fp16 anyway).
//   S = (Qh+Ql)@Kh: 2-term.  PV: 1-term.  Out-proj: 1-term.
// ---------------------------------------------------------------------------
__device__ float g_cos[SEQ*32];
__device__ float g_sin[SEQ*32];

__device__ __half g_Xh[(size_t)MTOT*DM];
__device__ __half g_Xl[(size_t)MTOT*DM];
__device__ __half g_Wh[(size_t)4096*DM];   // rows: WQ(0) WK(1024) WV(2048) WO(3072), hi only
__device__ __half g_Ath[(size_t)MTOT*DM];  // attention out, hi only (A-operand of out-proj)

// Q hi+lo (A-operand of S); K,V hi only (B-operands). [b,h,s,d]; Q pre-scaled 1/8.
__device__ __half g_Qh[(size_t)BQ*NH*SEQ*DKH];
__device__ __half g_Ql[(size_t)BQ*NH*SEQ*DKH];
__device__ __half g_Kh[(size_t)BQ*NH*SEQ*DKH];
__device__ __half g_Vh[(size_t)BQ*NH*SEQ*DKH];

// ---------------------------------------------------------------------------
// PTX helpers — portable (non-'a') instructions only.
// ---------------------------------------------------------------------------
__device__ __forceinline__ uint32_t smem_to_u32(const void* smem_ptr) {
    uint32_t addr;
    asm("{ .reg .u64 tmp; cvta.to.shared.u64 tmp, %1; cvt.u32.u64 %0, tmp; }"
        : "=r"(addr) : "l"(smem_ptr));
    return addr;
}

__device__ __forceinline__ void ldsm_x4(uint32_t* r, uint32_t addr) {
    asm volatile("ldmatrix.sync.aligned.m8n8.x4.shared.b16 {%0,%1,%2,%3}, [%4];"
        : "=r"(r[0]), "=r"(r[1]), "=r"(r[2]), "=r"(r[3]) : "r"(addr));
}
__device__ __forceinline__ void ldsm_x4_t(uint32_t* r, uint32_t addr) {
    asm volatile("ldmatrix.sync.aligned.m8n8.x4.trans.shared.b16 {%0,%1,%2,%3}, [%4];"
        : "=r"(r[0]), "=r"(r[1]), "=r"(r[2]), "=r"(r[3]) : "r"(addr));
}

__device__ __forceinline__ void mma_f16(float* d, const uint32_t* a, const uint32_t* b) {
    asm volatile(
        "mma.sync.aligned.m16n8k16.row.col.f32.f16.f16.f32 "
        "{%0,%1,%2,%3}, {%4,%5,%6,%7}, {%8,%9}, {%0,%1,%2,%3};"
        : "+f"(d[0]), "+f"(d[1]), "+f"(d[2]), "+f"(d[3])
        : "r"(a[0]), "r"(a[1]), "r"(a[2]), "r"(a[3]), "r"(b[0]), "r"(b[1]));
}

__device__ __forceinline__ void cp16(void* smem_dst, const void* gsrc) {
    uint32_t d = smem_to_u32(smem_dst);
    asm volatile("cp.async.cg.shared.global [%0], [%1], 16;" :: "r"(d), "l"(gsrc));
}
#define CP_COMMIT() asm volatile("cp.async.commit_group;" ::: "memory")
#define CP_WAIT0()  asm volatile("cp.async.wait_group 0;" ::: "memory")
#define CP_WAIT1()  asm volatile("cp.async.wait_group 1;" ::: "memory")

// split fp32 pair -> fp16 hi/lo arrays (4B vectorized stores)
__device__ __forceinline__ void store_split2(__half* hp, __half* lp,
                                             size_t off, float a, float b)
{
    __half2 hv;
    hv.x = __float2half(a);
    hv.y = __float2half(b);
    __half2 lv;
    lv.x = __float2half(a - __half2float(hv.x));
    lv.y = __float2half(b - __half2float(hv.y));
    *(__half2*)(hp + off) = hv;
    *(__half2*)(lp + off) = lv;
}

// ---------------------------------------------------------------------------
// RoPE tables
// ---------------------------------------------------------------------------
__global__ void rope_table_kernel(const int* __restrict__ pos)
{
    int idx = blockIdx.x * blockDim.x + threadIdx.x;
    if (idx >= SEQ*32) return;
    int s = idx >> 5;
    int p = idx & 31;
    int position = pos[s];
    double freq = pow(10000.0, -(double)(2*p) / 64.0);
    float ang = (float)position * (float)freq;   // fp32 multiply like the ref
    g_cos[idx] = (float)cos((double)ang);
    g_sin[idx] = (float)sin((double)ang);
}

// ---------------------------------------------------------------------------
// fp32 -> fp16 splits
// ---------------------------------------------------------------------------
__device__ __forceinline__ void split1(float v, __half& h, __half& l)
{
    h = __float2half(v);
    l = __float2half(v - __half2float(h));
}

union Pack4 { __half b[4]; uint2 u; };

__global__ void split_x_kernel(const float* __restrict__ in)   // 8M elems, hi+lo
{
    size_t i = blockIdx.x * (size_t)blockDim.x + threadIdx.x;
    float4 v = ((const float4*)in)[i];
    Pack4 uh, ul;
    split1(v.x, uh.b[0], ul.b[0]);
    split1(v.y, uh.b[1], ul.b[1]);
    split1(v.z, uh.b[2], ul.b[2]);
    split1(v.w, uh.b[3], ul.b[3]);
    ((uint2*)g_Xh)[i] = uh.u;
    ((uint2*)g_Xl)[i] = ul.u;
}

// all four weight matrices, HI ONLY: grid 4096, matrix = blockIdx.x>>10
__global__ void split_w_kernel(const float* __restrict__ w0, const float* __restrict__ w1,
                               const float* __restrict__ w2, const float* __restrict__ w3)
{
    int mat = blockIdx.x >> 10;
    const float* in = (mat == 0) ? w0 : (mat == 1) ? w1 : (mat == 2) ? w2 : w3;
    size_t li = ((size_t)(blockIdx.x & 1023)) * blockDim.x + threadIdx.x;
    float4 v = ((const float4*)in)[li];
    Pack4 uh;
    uh.b[0] = __float2half(v.x);
    uh.b[1] = __float2half(v.y);
    uh.b[2] = __float2half(v.z);
    uh.b[3] = __float2half(v.w);
    size_t o = (size_t)mat * 262144 + li;    // 1024*1024/4 per matrix
    ((uint2*)g_Wh)[o] = uh.u;
}

// ---------------------------------------------------------------------------
// fp16 GEMM on mma.sync: C = Ah@Bh (+ Al@Bh only for Q-projection blocks).
// 3-STAGE cp.async ring (stage fits since 1-term diet), issue-after-barrier,
// TWO CTAs per SM (3 x 30720 x 2 = 184320 <= 228KB), term-major order.
//   Block 128x128, BK=32, 8 warps (4m x 2n), warp tile 32x64.
// MODE 0: A = x-split, W rows [0,3072); epilogue RoPE (+1/8 for Q);
//         Q blocks (n0<1024): 2-term, hi+lo store. K/V blocks: 1-term, hi.
// MODE 1: A = g_Ath, W rows [3072,4096); 1-term; fp32 d_out.
// ---------------------------------------------------------------------------
#define PAD_HALF 40                 // smem row stride in halves (80 bytes)
#define GT_TILE  (128*PAD_HALF*2)   // 10240 B per tile
#define GT_STAGE (3*GT_TILE)        // 30720 B
#define GT_NSTG  3
#define GT_SMEM  (GT_NSTG*GT_STAGE) // 92160 B

template<int MODE>
__global__ __launch_bounds__(256, 2)
void gemm_mma(float* __restrict__ Cout)
{
    extern __shared__ __align__(16) char gsm[];

    const int tid  = threadIdx.x;
    const int wid  = tid >> 5;
    const int lane = tid & 31;
    const int m0 = blockIdx.y * 128;
    const int n0 = blockIdx.x * 128;
    const int brow = (MODE == 0) ? n0 : (3072 + n0);
    const bool useAl = (MODE == 0) && (n0 < 1024);   // 2-term only for Q blocks

    const __half* Ah = (MODE == 0) ? g_Xh : g_Ath;
    const __half* Al = g_Xl;                          // only read when useAl

    const int warp_m0 = (wid & 3) * 32;
    const int warp_n0 = (wid >> 2) * 64;

    const uint32_t aRow = warp_m0 + (lane & 15);
    const uint32_t aCol = (lane >> 4) * 8;
    const uint32_t aOff = (aRow * PAD_HALF + aCol) * 2;
    const uint32_t nRow = (lane & 7) | ((lane & 16) >> 1);
    const uint32_t kCol = ((lane >> 3) & 1) * 8;
    const uint32_t bOff = ((warp_n0 + nRow) * PAD_HALF + kCol) * 2;

    // precomputed load addressing (same every chunk)
    const int ldRow  = tid >> 2;            // 0..63 (+64 on second unit)
    const int ldSegb = (tid & 3) * 16;
    const uint32_t so0 = (uint32_t)(ldRow * (PAD_HALF*2) + ldSegb);
    const uint32_t so1 = (uint32_t)((ldRow + 64) * (PAD_HALF*2) + ldSegb);

    // issue cp.async loads of chunk ch into stage ch%3 (Ah, [Al], Bh)
    auto issueG = [&](int ch) {
        char* st = gsm + (ch % GT_NSTG) * GT_STAGE;
        const int k0b = ch * 64;
        size_t gA0 = (size_t)(m0 + ldRow) * 2048 + k0b + ldSegb;
        size_t gA1 = gA0 + (size_t)64 * 2048;
        size_t gB0 = (size_t)(brow + ldRow) * 2048 + k0b + ldSegb;
        size_t gB1 = gB0 + (size_t)64 * 2048;
        cp16(st + 0*GT_TILE + so0, (const char*)Ah   + gA0);
        cp16(st + 0*GT_TILE + so1, (const char*)Ah   + gA1);
        if (useAl) {
            cp16(st + 1*GT_TILE + so0, (const char*)Al + gA0);
            cp16(st + 1*GT_TILE + so1, (const char*)Al + gA1);
        }
        cp16(st + 2*GT_TILE + so0, (const char*)g_Wh + gB0);
        cp16(st + 2*GT_TILE + so1, (const char*)g_Wh + gB1);
        CP_COMMIT();
    };

    float acc[2][8][4];
#pragma unroll
    for (int i = 0; i < 2; i++)
#pragma unroll
        for (int j = 0; j < 8; j++)
#pragma unroll
            for (int c = 0; c < 4; c++) acc[i][j][c] = 0.f;

    issueG(0);
    issueG(1);

    for (int ch = 0; ch < 32; ch++) {
        if (ch == 31) { CP_WAIT0(); } else { CP_WAIT1(); }  // chunk ch resident
        __syncthreads();            // readers of stage (ch+2)%3 (chunk ch-1) done
        if (ch + 2 < 32) issueG(ch + 2);

        const uint32_t stb = smem_to_u32(gsm + (ch % GT_NSTG) * GT_STAGE);
        const uint32_t bAh = stb + 0*GT_TILE;
        const uint32_t bAl = stb + 1*GT_TILE;
        const uint32_t bBh = stb + 2*GT_TILE;

#pragma unroll
        for (int ks = 0; ks < 2; ks++) {
            const uint32_t kb = ks * 32;
            uint32_t ahf[2][4], alf[2][4];
            uint32_t bh4[4][4];
#pragma unroll
            for (int mi = 0; mi < 2; mi++)
                ldsm_x4(ahf[mi], bAh + aOff + mi * (16*PAD_HALF*2) + kb);
            if (useAl) {
#pragma unroll
                for (int mi = 0; mi < 2; mi++)
                    ldsm_x4(alf[mi], bAl + aOff + mi * (16*PAD_HALF*2) + kb);
            }
#pragma unroll
            for (int nj = 0; nj < 4; nj++)
                ldsm_x4(bh4[nj], bBh + bOff + nj * (16*PAD_HALF*2) + kb);
            // term-major mma stream (hi term; then lo term when used)
#pragma unroll
            for (int nj = 0; nj < 4; nj++)
#pragma unroll
                for (int mi = 0; mi < 2; mi++)
#pragma unroll
                    for (int sub = 0; sub < 2; sub++)
                        mma_f16(acc[mi][nj*2 + sub], ahf[mi], &bh4[nj][sub*2]);
            if (useAl) {
#pragma unroll
                for (int nj = 0; nj < 4; nj++)
#pragma unroll
                    for (int mi = 0; mi < 2; mi++)
#pragma unroll
                        for (int sub = 0; sub < 2; sub++)
                            mma_f16(acc[mi][nj*2 + sub], alf[mi], &bh4[nj][sub*2]);
            }
        }
    }

    const int mrow0 = m0 + warp_m0 + (lane >> 2);
    const int ncol0 = n0 + warp_n0 + 2 * (lane & 3);

    if (MODE == 0) {
        const int sel = n0 >> 10;                       // 0:Q 1:K 2:V
        __half* hp = (sel == 0) ? g_Qh : (sel == 1) ? g_Kh : g_Vh;
        const float sc_q = (sel == 0) ? 0.125f : 1.0f;  // fold 1/sqrt(d_k) into Q
#pragma unroll
        for (int mi = 0; mi < 2; mi++)
#pragma unroll
            for (int nt = 0; nt < 8; nt++) {
                int ngl = ncol0 + nt * 8;
                int o = ngl & 1023;
                int h = o >> 6, d = o & 63;             // d even
#pragma unroll
                for (int dr = 0; dr < 2; dr++) {
                    int m = mrow0 + mi * 16 + dr * 8;
                    int b = m >> 11, s = m & 2047;
                    size_t di = ((size_t)(b * 16 + h) * 2048 + s) * 64 + d;
                    float e  = acc[mi][nt][dr * 2];
                    float od = acc[mi][nt][dr * 2 + 1];
                    if (sel < 2) {
                        float cs = g_cos[s * 32 + (d >> 1)];
                        float sn = g_sin[s * 32 + (d >> 1)];
                        float e2 = (e * cs - od * sn) * sc_q;
                        od = (e * sn + od * cs) * sc_q;
                        e = e2;
                    }
                    if (sel == 0) {
                        store_split2(g_Qh, g_Ql, di, e, od);   // Q: hi+lo
                    } else {
                        __half2 hv;                            // K/V: hi only
                        hv.x = __float2half(e);
                        hv.y = __float2half(od);
                        *(__half2*)(hp + di) = hv;
                    }
                }
            }
    } else {
#pragma unroll
        for (int mi = 0; mi < 2; mi++)
#pragma unroll
            for (int nt = 0; nt < 8; nt++) {
                int ngl = ncol0 + nt * 8;
#pragma unroll
                for (int dr = 0; dr < 2; dr++) {
                    int m = mrow0 + mi * 16 + dr * 8;
                    *(float2*)(Cout + (size_t)m * 1024 + ngl) =
                        make_float2(acc[mi][nt][dr * 2], acc[mi][nt][dr * 2 + 1]);
                }
            }
    }
}

// ---------------------------------------------------------------------------
// Causal flash attention: S = (Qh+Ql)@Kh (2-term); O = Ph@Vh (1-term).
// TWO CTAs per SM now (smem 36864 x 2 = 73728): cross-CTA overlap hides the
// mma<->softmax phase alternation. Key tiles of 64, cp.async 2-stage.
// Q pre-scaled by 1/8. Epilogue stores hi-only attention output.
// ---------------------------------------------------------------------------
#define APAD 72                  // halves; 144B stride (conflict-free ldmatrix)
#define KV_STAGE_BYTES (2*64*APAD*2)   // 18432
#define ATTN_SMEM (2*KV_STAGE_BYTES)   // 36864

__global__ __launch_bounds__(256, 2)
void attn_mma()
{
    extern __shared__ __align__(16) char dsm[];

    const int tid  = threadIdx.x;
    const int wid  = tid >> 5;
    const int lane = tid & 31;
    const int bh = blockIdx.y;                       // b*16 + h
    const int qi = (int)gridDim.x - 1 - (int)blockIdx.x;  // heavy blocks first
    const int q0 = qi * 128;
    const size_t base = (size_t)bh * SEQ * DKH;      // element offset

    // ---- Load Q tile (128 x 64 halves, hi/lo) into stage area, frag to regs
    __half* sQh = (__half*)dsm;
    __half* sQl = (__half*)dsm + 128*APAD;           // 36864 B, fits
#pragma unroll
    for (int u = 0; u < 4; u++) {
        int unit = tid + u * 256;                    // 1024 units per array
        int row = unit >> 3, seg = (unit & 7) * 8;
        size_t g = base + (size_t)(q0 + row) * 64 + seg;
        *(uint4*)(sQh + row * APAD + seg) = *(const uint4*)(g_Qh + g);
        *(uint4*)(sQl + row * APAD + seg) = *(const uint4*)(g_Ql + g);
    }
    __syncthreads();

    uint32_t qfh[4][4], qfl[4][4];
    {
        const int aRow = wid * 16 + (lane & 15);
        const int aCol = (lane >> 4) * 8;
#pragma unroll
        for (int kt = 0; kt < 4; kt++) {
            ldsm_x4(qfh[kt], smem_to_u32(sQh + aRow * APAD + kt * 16 + aCol));
            ldsm_x4(qfl[kt], smem_to_u32(sQl + aRow * APAD + kt * 16 + aCol));
        }
    }
    __syncthreads();   // Q consumed; smem stages free

    float o[8][4];
#pragma unroll
    for (int j = 0; j < 8; j++)
#pragma unroll
        for (int c = 0; c < 4; c++) o[j][c] = 0.f;
    float m0r = -INFINITY, m1r = -INFINITY;
    float l0 = 0.f, l1 = 0.f;

    const int ntiles = q0 / 64 + 2;

    // prefetch tile t into stage t&1 (Kh + Vh)
    auto issue = [&](int t) {
        const int k0 = t * 64;
        char* st = dsm + (t & 1) * KV_STAGE_BYTES;
        __half* dKh = (__half*)st;
        __half* dVh = (__half*)st + 64*APAD;
#pragma unroll
        for (int u = 0; u < 2; u++) {
            int unit = tid + u * 256;                // 512 units per array
            int row = unit >> 3, seg = (unit & 7) * 8;
            size_t g = base + (size_t)(k0 + row) * 64 + seg;
            int so = row * APAD + seg;
            cp16(dKh + so, g_Kh + g);
            cp16(dVh + so, g_Vh + g);
        }
        CP_COMMIT();
    };

    issue(0);

    const int bRow = (lane & 7) | ((lane & 16) >> 1);
    const int bK   = ((lane >> 3) & 1) * 8;
    const int vRowSel = (lane & 7) + ((lane >> 3) & 1) * 8;
    const int vColSel = ((lane >> 4) & 1) * 8;
    const int qrow0 = q0 + wid * 16 + (lane >> 2);

    for (int t = 0; t < ntiles; t++) {
        CP_WAIT0();
        __syncthreads();
        if (t + 1 < ntiles) issue(t + 1);

        const int k0 = t * 64;
        char* st = dsm + (t & 1) * KV_STAGE_BYTES;
        const __half* sKh = (const __half*)st;
        const __half* sVh = (const __half*)st + 64*APAD;

        // ---- S = Q K^T (2-term, term-major over njp pairs)
        float s[8][4];
#pragma unroll
        for (int j = 0; j < 8; j++)
#pragma unroll
            for (int c = 0; c < 4; c++) s[j][c] = 0.f;

#pragma unroll
        for (int ks = 0; ks < 4; ks++)
#pragma unroll
            for (int nj2 = 0; nj2 < 2; nj2++) {          // pairs of 16-col K tiles
                uint32_t kh4[2][4];
#pragma unroll
                for (int p = 0; p < 2; p++) {
                    int njp = nj2 * 2 + p;
                    ldsm_x4(kh4[p], smem_to_u32(sKh + (njp * 16 + bRow) * APAD + ks * 16 + bK));
                }
#pragma unroll
                for (int p = 0; p < 2; p++)
#pragma unroll
                    for (int sub = 0; sub < 2; sub++)
                        mma_f16(s[(nj2*2 + p)*2 + sub], qfh[ks], &kh4[p][sub*2]);
#pragma unroll
                for (int p = 0; p < 2; p++)
#pragma unroll
                    for (int sub = 0; sub < 2; sub++)
                        mma_f16(s[(nj2*2 + p)*2 + sub], qfl[ks], &kh4[p][sub*2]);
            }

        // ---- causal mask (scores already scaled via Q)
        if (k0 + 63 > q0 + wid * 16) {
#pragma unroll
            for (int j = 0; j < 8; j++)
#pragma unroll
                for (int c = 0; c < 4; c++) {
                    int key = k0 + j * 8 + 2 * (lane & 3) + (c & 1);
                    int row = qrow0 + ((c & 2) ? 8 : 0);
                    if (key > row) s[j][c] = -INFINITY;
                }
        }

        // ---- row max (rows r0 = regs 0,1; r0+8 = regs 2,3)
        float tm0 = -INFINITY, tm1 = -INFINITY;
#pragma unroll
        for (int j = 0; j < 8; j++) {
            tm0 = fmaxf(tm0, fmaxf(s[j][0], s[j][1]));
            tm1 = fmaxf(tm1, fmaxf(s[j][2], s[j][3]));
        }
        tm0 = fmaxf(tm0, __shfl_xor_sync(0xffffffffu, tm0, 1));
        tm0 = fmaxf(tm0, __shfl_xor_sync(0xffffffffu, tm0, 2));
        tm1 = fmaxf(tm1, __shfl_xor_sync(0xffffffffu, tm1, 1));
        tm1 = fmaxf(tm1, __shfl_xor_sync(0xffffffffu, tm1, 2));

        float mn0 = fmaxf(m0r, tm0), mn1 = fmaxf(m1r, tm1);
        float c0 = __expf(m0r - mn0), c1 = __expf(m1r - mn1);
        m0r = mn0; m1r = mn1;

        // ---- exp, pack P hi-only A-fragments, row sums
        float rs0 = 0.f, rs1 = 0.f;
        uint32_t ph[4][4];
#pragma unroll
        for (int j = 0; j < 4; j++) {
            float p[2][4];   // [ntile 2j / 2j+1][reg]
#pragma unroll
            for (int e = 0; e < 2; e++) {
                int nj = 2 * j + e;
                p[e][0] = __expf(s[nj][0] - mn0);
                p[e][1] = __expf(s[nj][1] - mn0);
                p[e][2] = __expf(s[nj][2] - mn1);
                p[e][3] = __expf(s[nj][3] - mn1);
                rs0 += p[e][0] + p[e][1];
                rs1 += p[e][2] + p[e][3];
            }
#pragma unroll
            for (int e = 0; e < 2; e++)
#pragma unroll
                for (int half = 0; half < 2; half++) {
                    __half2 hv;
                    hv.x = __float2half(p[e][half * 2 + 0]);
                    hv.y = __float2half(p[e][half * 2 + 1]);
                    ph[j][e * 2 + half] = *(uint32_t*)&hv;
                }
        }
        rs0 += __shfl_xor_sync(0xffffffffu, rs0, 1);
        rs0 += __shfl_xor_sync(0xffffffffu, rs0, 2);
        rs1 += __shfl_xor_sync(0xffffffffu, rs1, 1);
        rs1 += __shfl_xor_sync(0xffffffffu, rs1, 2);
        l0 = l0 * c0 + rs0;
        l1 = l1 * c1 + rs1;

        // ---- rescale O
#pragma unroll
        for (int j = 0; j < 8; j++) {
            o[j][0] *= c0; o[j][1] *= c0;
            o[j][2] *= c1; o[j][3] *= c1;
        }

        // ---- O += P V (1-term, term-major over vjp pairs), V via ldmatrix.trans
#pragma unroll
        for (int kt = 0; kt < 4; kt++)
#pragma unroll
            for (int vj2 = 0; vj2 < 2; vj2++) {
                uint32_t vh4[2][4];
#pragma unroll
                for (int p = 0; p < 2; p++) {
                    int vjp = vj2 * 2 + p;
                    int vrow = kt * 16 + vRowSel;
                    int vcol = vjp * 16 + vColSel;
                    ldsm_x4_t(vh4[p], smem_to_u32(sVh + vrow * APAD + vcol));
                }
#pragma unroll
                for (int p = 0; p < 2; p++)
#pragma unroll
                    for (int sub = 0; sub < 2; sub++)
                        mma_f16(o[(vj2*2 + p)*2 + sub], ph[kt], &vh4[p][sub*2]);
            }
        __syncthreads();   // stage consumed before refill in next iteration
    }

    // ---- epilogue: normalize, hi-only store to g_Ath
    float inv0 = 1.f / l0, inv1 = 1.f / l1;
    const int b = bh >> 4, h = bh & 15;
    const int s0 = q0 + wid * 16 + (lane >> 2);
#pragma unroll
    for (int nj = 0; nj < 8; nj++) {
        int col = h * 64 + nj * 8 + 2 * (lane & 3);
        size_t off0 = ((size_t)(b * 2048 + s0)) * 1024 + col;
        size_t off1 = ((size_t)(b * 2048 + s0 + 8)) * 1024 + col;
        __half2 h0, h1;
        h0.x = __float2half(o[nj][0] * inv0);
        h0.y = __float2half(o[nj][1] * inv0);
        h1.x = __float2half(o[nj][2] * inv1);
        h1.y = __float2half(o[nj][3] * inv1);
        *(__half2*)(g_Ath + off0) = h0;
        *(__half2*)(g_Ath + off1) = h1;
    }
}

// ---------------------------------------------------------------------------
extern "C" void kernel_launch(void* const* d_in, const int* in_sizes, int n_in,
                              void* d_out, int out_size)
{
    const float* x  = (const float*)d_in[0];
    const float* WQ = (const float*)d_in[1];
    const float* WK = (const float*)d_in[2];
    const float* WV = (const float*)d_in[3];
    const float* WO = (const float*)d_in[4];
    const int*  pos = (const int*)d_in[5];
    float* out = (float*)d_out;

    cudaFuncSetAttribute(attn_mma, cudaFuncAttributeMaxDynamicSharedMemorySize, ATTN_SMEM);
    cudaFuncSetAttribute(gemm_mma<0>, cudaFuncAttributeMaxDynamicSharedMemorySize, GT_SMEM);
    cudaFuncSetAttribute(gemm_mma<1>, cudaFuncAttributeMaxDynamicSharedMemorySize, GT_SMEM);

    // 1) RoPE tables
    rope_table_kernel<<<(SEQ*32 + 255)/256, 256>>>(pos);

    // 2) fp16 splits of X (hi+lo) and weights (hi only)
    split_x_kernel<<<8192, 256>>>(x);
    split_w_kernel<<<4096, 256>>>(WQ, WK, WV, WO);

    // 3) Fused QKV projection + RoPE; Q 2-term -> hi+lo (x1/8), K/V 1-term -> hi
    gemm_mma<0><<<dim3(24, 64), 256, GT_SMEM>>>(nullptr);

    // 4) Causal flash attention (S 2-term, PV 1-term, 2 CTAs/SM); writes g_Ath
    attn_mma<<<dim3(SEQ/128, BQ*NH), 256, ATTN_SMEM>>>();

    // 5) Output projection (1-term)
    gemm_mma<1><<<dim3(8, 64), 256, GT_SMEM>>>(out);
}

// round 16
// speedup vs baseline: 1.0184x; 1.0184x over previous
#include <cuda_runtime.h>
#include <cuda_fp16.h>
#include <math.h>
#include <stdint.h>

// Problem constants
#define BQ   4
#define SEQ  2048
#define DM   1024
#define NH   16
#define DKH  64
#define MTOT (BQ*SEQ)   // 8192

// ---------------------------------------------------------------------------
// Scratch (device globals: allocation-free)
// fp16 mixed-precision scheme (calibrated: sigma ~1.9e-4 per rounding source):
//   X: hi+lo.  Q projection: 2-term (feeds exponentiated scores).
//   K/V projections: 1-term (outputs rounded to fp16 anyway).
//   S = (Qh+Ql)@Kh: 2-term.  PV: 1-term.  Out-proj: 1-term.
// ---------------------------------------------------------------------------
__device__ float g_cos[SEQ*32];
__device__ float g_sin[SEQ*32];

__device__ __half g_Xh[(size_t)MTOT*DM];
__device__ __half g_Xl[(size_t)MTOT*DM];
__device__ __half g_Wh[(size_t)4096*DM];   // rows: WQ(0) WK(1024) WV(2048) WO(3072), hi only
__device__ __half g_Ath[(size_t)MTOT*DM];  // attention out, hi only (A-operand of out-proj)

// Q hi+lo (A-operand of S); K,V hi only (B-operands). [b,h,s,d]; Q pre-scaled 1/8.
__device__ __half g_Qh[(size_t)BQ*NH*SEQ*DKH];
__device__ __half g_Ql[(size_t)BQ*NH*SEQ*DKH];
__device__ __half g_Kh[(size_t)BQ*NH*SEQ*DKH];
__device__ __half g_Vh[(size_t)BQ*NH*SEQ*DKH];

// ---------------------------------------------------------------------------
// PTX helpers — portable (non-'a') instructions only.
// ---------------------------------------------------------------------------
__device__ __forceinline__ uint32_t smem_to_u32(const void* smem_ptr) {
    uint32_t addr;
    asm("{ .reg .u64 tmp; cvta.to.shared.u64 tmp, %1; cvt.u32.u64 %0, tmp; }"
        : "=r"(addr) : "l"(smem_ptr));
    return addr;
}

__device__ __forceinline__ void ldsm_x4(uint32_t* r, uint32_t addr) {
    asm volatile("ldmatrix.sync.aligned.m8n8.x4.shared.b16 {%0,%1,%2,%3}, [%4];"
        : "=r"(r[0]), "=r"(r[1]), "=r"(r[2]), "=r"(r[3]) : "r"(addr));
}
__device__ __forceinline__ void ldsm_x4_t(uint32_t* r, uint32_t addr) {
    asm volatile("ldmatrix.sync.aligned.m8n8.x4.trans.shared.b16 {%0,%1,%2,%3}, [%4];"
        : "=r"(r[0]), "=r"(r[1]), "=r"(r[2]), "=r"(r[3]) : "r"(addr));
}

__device__ __forceinline__ void mma_f16(float* d, const uint32_t* a, const uint32_t* b) {
    asm volatile(
        "mma.sync.aligned.m16n8k16.row.col.f32.f16.f16.f32 "
        "{%0,%1,%2,%3}, {%4,%5,%6,%7}, {%8,%9}, {%0,%1,%2,%3};"
        : "+f"(d[0]), "+f"(d[1]), "+f"(d[2]), "+f"(d[3])
        : "r"(a[0]), "r"(a[1]), "r"(a[2]), "r"(a[3]), "r"(b[0]), "r"(b[1]));
}

__device__ __forceinline__ void cp16(void* smem_dst, const void* gsrc) {
    uint32_t d = smem_to_u32(smem_dst);
    asm volatile("cp.async.cg.shared.global [%0], [%1], 16;" :: "r"(d), "l"(gsrc));
}
#define CP_COMMIT() asm volatile("cp.async.commit_group;" ::: "memory")
#define CP_WAIT0()  asm volatile("cp.async.wait_group 0;" ::: "memory")
#define CP_WAIT1()  asm volatile("cp.async.wait_group 1;" ::: "memory")

// split fp32 pair -> fp16 hi/lo arrays (4B vectorized stores)
__device__ __forceinline__ void store_split2(__half* hp, __half* lp,
                                             size_t off, float a, float b)
{
    __half2 hv;
    hv.x = __float2half(a);
    hv.y = __float2half(b);
    __half2 lv;
    lv.x = __float2half(a - __half2float(hv.x));
    lv.y = __float2half(b - __half2float(hv.y));
    *(__half2*)(hp + off) = hv;
    *(__half2*)(lp + off) = lv;
}

// ---------------------------------------------------------------------------
// RoPE tables
// ---------------------------------------------------------------------------
__global__ void rope_table_kernel(const int* __restrict__ pos)
{
    int idx = blockIdx.x * blockDim.x + threadIdx.x;
    if (idx >= SEQ*32) return;
    int s = idx >> 5;
    int p = idx & 31;
    int position = pos[s];
    double freq = pow(10000.0, -(double)(2*p) / 64.0);
    float ang = (float)position * (float)freq;   // fp32 multiply like the ref
    g_cos[idx] = (float)cos((double)ang);
    g_sin[idx] = (float)sin((double)ang);
}

// ---------------------------------------------------------------------------
// fp32 -> fp16 splits
// ---------------------------------------------------------------------------
__device__ __forceinline__ void split1(float v, __half& h, __half& l)
{
    h = __float2half(v);
    l = __float2half(v - __half2float(h));
}

union Pack4 { __half b[4]; uint2 u; };

__global__ void split_x_kernel(const float* __restrict__ in)   // 8M elems, hi+lo
{
    size_t i = blockIdx.x * (size_t)blockDim.x + threadIdx.x;
    float4 v = ((const float4*)in)[i];
    Pack4 uh, ul;
    split1(v.x, uh.b[0], ul.b[0]);
    split1(v.y, uh.b[1], ul.b[1]);
    split1(v.z, uh.b[2], ul.b[2]);
    split1(v.w, uh.b[3], ul.b[3]);
    ((uint2*)g_Xh)[i] = uh.u;
    ((uint2*)g_Xl)[i] = ul.u;
}

// all four weight matrices, HI ONLY: grid 4096, matrix = blockIdx.x>>10
__global__ void split_w_kernel(const float* __restrict__ w0, const float* __restrict__ w1,
                               const float* __restrict__ w2, const float* __restrict__ w3)
{
    int mat = blockIdx.x >> 10;
    const float* in = (mat == 0) ? w0 : (mat == 1) ? w1 : (mat == 2) ? w2 : w3;
    size_t li = ((size_t)(blockIdx.x & 1023)) * blockDim.x + threadIdx.x;
    float4 v = ((const float4*)in)[li];
    Pack4 uh;
    uh.b[0] = __float2half(v.x);
    uh.b[1] = __float2half(v.y);
    uh.b[2] = __float2half(v.z);
    uh.b[3] = __float2half(v.w);
    size_t o = (size_t)mat * 262144 + li;    // 1024*1024/4 per matrix
    ((uint2*)g_Wh)[o] = uh.u;
}

// ---------------------------------------------------------------------------
// fp16 GEMM on mma.sync: C = Ah@Bh (+ Al@Bh only for Q-projection blocks).
// 2-STAGE cp.async ring (3-stage regressed twice: R7, R15), issue-after-
// barrier, TWO CTAs per SM, term-major order.
//   Block 128x128, BK=32, 8 warps (4m x 2n), warp tile 32x64.
// MODE 0: A = x-split, W rows [0,3072); epilogue RoPE (+1/8 for Q);
//         Q blocks (n0<1024): 2-term, hi+lo store. K/V blocks: 1-term, hi.
// MODE 1: A = g_Ath, W rows [3072,4096); 1-term; fp32 d_out.
// ---------------------------------------------------------------------------
#define PAD_HALF 40                 // smem row stride in halves (80 bytes)
#define GT_TILE  (128*PAD_HALF*2)   // 10240 B per tile
#define GT_STAGE (3*GT_TILE)        // 30720 B
#define GT_SMEM  (2*GT_STAGE)       // 61440 B

template<int MODE>
__global__ __launch_bounds__(256, 2)
void gemm_mma(float* __restrict__ Cout)
{
    extern __shared__ __align__(16) char gsm[];

    const int tid  = threadIdx.x;
    const int wid  = tid >> 5;
    const int lane = tid & 31;
    const int m0 = blockIdx.y * 128;
    const int n0 = blockIdx.x * 128;
    const int brow = (MODE == 0) ? n0 : (3072 + n0);
    const bool useAl = (MODE == 0) && (n0 < 1024);   // 2-term only for Q blocks

    const __half* Ah = (MODE == 0) ? g_Xh : g_Ath;
    const __half* Al = g_Xl;                          // only read when useAl

    const int warp_m0 = (wid & 3) * 32;
    const int warp_n0 = (wid >> 2) * 64;

    const uint32_t aRow = warp_m0 + (lane & 15);
    const uint32_t aCol = (lane >> 4) * 8;
    const uint32_t aOff = (aRow * PAD_HALF + aCol) * 2;
    const uint32_t nRow = (lane & 7) | ((lane & 16) >> 1);
    const uint32_t kCol = ((lane >> 3) & 1) * 8;
    const uint32_t bOff = ((warp_n0 + nRow) * PAD_HALF + kCol) * 2;

    // precomputed load addressing (same every chunk)
    const int ldRow  = tid >> 2;            // 0..63 (+64 on second unit)
    const int ldSegb = (tid & 3) * 16;
    const uint32_t so0 = (uint32_t)(ldRow * (PAD_HALF*2) + ldSegb);
    const uint32_t so1 = (uint32_t)((ldRow + 64) * (PAD_HALF*2) + ldSegb);

    // issue cp.async loads of chunk ch into stage ch&1 (Ah, [Al], Bh)
    auto issueG = [&](int ch) {
        char* st = gsm + (ch & 1) * GT_STAGE;
        const int k0b = ch * 64;
        size_t gA0 = (size_t)(m0 + ldRow) * 2048 + k0b + ldSegb;
        size_t gA1 = gA0 + (size_t)64 * 2048;
        size_t gB0 = (size_t)(brow + ldRow) * 2048 + k0b + ldSegb;
        size_t gB1 = gB0 + (size_t)64 * 2048;
        cp16(st + 0*GT_TILE + so0, (const char*)Ah   + gA0);
        cp16(st + 0*GT_TILE + so1, (const char*)Ah   + gA1);
        if (useAl) {
            cp16(st + 1*GT_TILE + so0, (const char*)Al + gA0);
            cp16(st + 1*GT_TILE + so1, (const char*)Al + gA1);
        }
        cp16(st + 2*GT_TILE + so0, (const char*)g_Wh + gB0);
        cp16(st + 2*GT_TILE + so1, (const char*)g_Wh + gB1);
        CP_COMMIT();
    };

    float acc[2][8][4];
#pragma unroll
    for (int i = 0; i < 2; i++)
#pragma unroll
        for (int j = 0; j < 8; j++)
#pragma unroll
            for (int c = 0; c < 4; c++) acc[i][j][c] = 0.f;

    issueG(0);

    for (int ch = 0; ch < 32; ch++) {
        CP_WAIT0();
        __syncthreads();
        if (ch + 1 < 32) issueG(ch + 1);

        const uint32_t stb = smem_to_u32(gsm + (ch & 1) * GT_STAGE);
        const uint32_t bAh = stb + 0*GT_TILE;
        const uint32_t bAl = stb + 1*GT_TILE;
        const uint32_t bBh = stb + 2*GT_TILE;

#pragma unroll
        for (int ks = 0; ks < 2; ks++) {
            const uint32_t kb = ks * 32;
            uint32_t ahf[2][4], alf[2][4];
            uint32_t bh4[4][4];
#pragma unroll
            for (int mi = 0; mi < 2; mi++)
                ldsm_x4(ahf[mi], bAh + aOff + mi * (16*PAD_HALF*2) + kb);
            if (useAl) {
#pragma unroll
                for (int mi = 0; mi < 2; mi++)
                    ldsm_x4(alf[mi], bAl + aOff + mi * (16*PAD_HALF*2) + kb);
            }
#pragma unroll
            for (int nj = 0; nj < 4; nj++)
                ldsm_x4(bh4[nj], bBh + bOff + nj * (16*PAD_HALF*2) + kb);
            // term-major mma stream (hi term; then lo term when used)
#pragma unroll
            for (int nj = 0; nj < 4; nj++)
#pragma unroll
                for (int mi = 0; mi < 2; mi++)
#pragma unroll
                    for (int sub = 0; sub < 2; sub++)
                        mma_f16(acc[mi][nj*2 + sub], ahf[mi], &bh4[nj][sub*2]);
            if (useAl) {
#pragma unroll
                for (int nj = 0; nj < 4; nj++)
#pragma unroll
                    for (int mi = 0; mi < 2; mi++)
#pragma unroll
                        for (int sub = 0; sub < 2; sub++)
                            mma_f16(acc[mi][nj*2 + sub], alf[mi], &bh4[nj][sub*2]);
            }
        }
    }

    const int mrow0 = m0 + warp_m0 + (lane >> 2);
    const int ncol0 = n0 + warp_n0 + 2 * (lane & 3);

    if (MODE == 0) {
        const int sel = n0 >> 10;                       // 0:Q 1:K 2:V
        __half* hp = (sel == 0) ? g_Qh : (sel == 1) ? g_Kh : g_Vh;
        const float sc_q = (sel == 0) ? 0.125f : 1.0f;  // fold 1/sqrt(d_k) into Q
#pragma unroll
        for (int mi = 0; mi < 2; mi++)
#pragma unroll
            for (int nt = 0; nt < 8; nt++) {
                int ngl = ncol0 + nt * 8;
                int o = ngl & 1023;
                int h = o >> 6, d = o & 63;             // d even
#pragma unroll
                for (int dr = 0; dr < 2; dr++) {
                    int m = mrow0 + mi * 16 + dr * 8;
                    int b = m >> 11, s = m & 2047;
                    size_t di = ((size_t)(b * 16 + h) * 2048 + s) * 64 + d;
                    float e  = acc[mi][nt][dr * 2];
                    float od = acc[mi][nt][dr * 2 + 1];
                    if (sel < 2) {
                        float cs = g_cos[s * 32 + (d >> 1)];
                        float sn = g_sin[s * 32 + (d >> 1)];
                        float e2 = (e * cs - od * sn) * sc_q;
                        od = (e * sn + od * cs) * sc_q;
                        e = e2;
                    }
                    if (sel == 0) {
                        store_split2(g_Qh, g_Ql, di, e, od);   // Q: hi+lo
                    } else {
                        __half2 hv;                            // K/V: hi only
                        hv.x = __float2half(e);
                        hv.y = __float2half(od);
                        *(__half2*)(hp + di) = hv;
                    }
                }
            }
    } else {
#pragma unroll
        for (int mi = 0; mi < 2; mi++)
#pragma unroll
            for (int nt = 0; nt < 8; nt++) {
                int ngl = ncol0 + nt * 8;
#pragma unroll
                for (int dr = 0; dr < 2; dr++) {
                    int m = mrow0 + mi * 16 + dr * 8;
                    *(float2*)(Cout + (size_t)m * 1024 + ngl) =
                        make_float2(acc[mi][nt][dr * 2], acc[mi][nt][dr * 2 + 1]);
                }
            }
    }
}

// ---------------------------------------------------------------------------
// Causal flash attention: S = (Qh+Ql)@Kh (2-term); O = Ph@Vh (1-term).
// TWO CTAs per SM (measured ~-3us vs 1 CTA). Key tiles of 64, cp.async 2-stage.
// Q pre-scaled by 1/8. Epilogue stores hi-only attention output.
// ---------------------------------------------------------------------------
#define APAD 72                  // halves; 144B stride (conflict-free ldmatrix)
#define KV_STAGE_BYTES (2*64*APAD*2)   // 18432
#define ATTN_SMEM (2*KV_STAGE_BYTES)   // 36864

__global__ __launch_bounds__(256, 2)
void attn_mma()
{
    extern __shared__ __align__(16) char dsm[];

    const int tid  = threadIdx.x;
    const int wid  = tid >> 5;
    const int lane = tid & 31;
    const int bh = blockIdx.y;                       // b*16 + h
    const int qi = (int)gridDim.x - 1 - (int)blockIdx.x;  // heavy blocks first
    const int q0 = qi * 128;
    const size_t base = (size_t)bh * SEQ * DKH;      // element offset

    // ---- Load Q tile (128 x 64 halves, hi/lo) into stage area, frag to regs
    __half* sQh = (__half*)dsm;
    __half* sQl = (__half*)dsm + 128*APAD;           // 36864 B, fits
#pragma unroll
    for (int u = 0; u < 4; u++) {
        int unit = tid + u * 256;                    // 1024 units per array
        int row = unit >> 3, seg = (unit & 7) * 8;
        size_t g = base + (size_t)(q0 + row) * 64 + seg;
        *(uint4*)(sQh + row * APAD + seg) = *(const uint4*)(g_Qh + g);
        *(uint4*)(sQl + row * APAD + seg) = *(const uint4*)(g_Ql + g);
    }
    __syncthreads();

    uint32_t qfh[4][4], qfl[4][4];
    {
        const int aRow = wid * 16 + (lane & 15);
        const int aCol = (lane >> 4) * 8;
#pragma unroll
        for (int kt = 0; kt < 4; kt++) {
            ldsm_x4(qfh[kt], smem_to_u32(sQh + aRow * APAD + kt * 16 + aCol));
            ldsm_x4(qfl[kt], smem_to_u32(sQl + aRow * APAD + kt * 16 + aCol));
        }
    }
    __syncthreads();   // Q consumed; smem stages free

    float o[8][4];
#pragma unroll
    for (int j = 0; j < 8; j++)
#pragma unroll
        for (int c = 0; c < 4; c++) o[j][c] = 0.f;
    float m0r = -INFINITY, m1r = -INFINITY;
    float l0 = 0.f, l1 = 0.f;

    const int ntiles = q0 / 64 + 2;

    // prefetch tile t into stage t&1 (Kh + Vh)
    auto issue = [&](int t) {
        const int k0 = t * 64;
        char* st = dsm + (t & 1) * KV_STAGE_BYTES;
        __half* dKh = (__half*)st;
        __half* dVh = (__half*)st + 64*APAD;
#pragma unroll
        for (int u = 0; u < 2; u++) {
            int unit = tid + u * 256;                // 512 units per array
            int row = unit >> 3, seg = (unit & 7) * 8;
            size_t g = base + (size_t)(k0 + row) * 64 + seg;
            int so = row * APAD + seg;
            cp16(dKh + so, g_Kh + g);
            cp16(dVh + so, g_Vh + g);
        }
        CP_COMMIT();
    };

    issue(0);

    const int bRow = (lane & 7) | ((lane & 16) >> 1);
    const int bK   = ((lane >> 3) & 1) * 8;
    const int vRowSel = (lane & 7) + ((lane >> 3) & 1) * 8;
    const int vColSel = ((lane >> 4) & 1) * 8;
    const int qrow0 = q0 + wid * 16 + (lane >> 2);

    for (int t = 0; t < ntiles; t++) {
        CP_WAIT0();
        __syncthreads();
        if (t + 1 < ntiles) issue(t + 1);

        const int k0 = t * 64;
        char* st = dsm + (t & 1) * KV_STAGE_BYTES;
        const __half* sKh = (const __half*)st;
        const __half* sVh = (const __half*)st + 64*APAD;

        // ---- S = Q K^T (2-term, term-major over njp pairs)
        float s[8][4];
#pragma unroll
        for (int j = 0; j < 8; j++)
#pragma unroll
            for (int c = 0; c < 4; c++) s[j][c] = 0.f;

#pragma unroll
        for (int ks = 0; ks < 4; ks++)
#pragma unroll
            for (int nj2 = 0; nj2 < 2; nj2++) {          // pairs of 16-col K tiles
                uint32_t kh4[2][4];
#pragma unroll
                for (int p = 0; p < 2; p++) {
                    int njp = nj2 * 2 + p;
                    ldsm_x4(kh4[p], smem_to_u32(sKh + (njp * 16 + bRow) * APAD + ks * 16 + bK));
                }
#pragma unroll
                for (int p = 0; p < 2; p++)
#pragma unroll
                    for (int sub = 0; sub < 2; sub++)
                        mma_f16(s[(nj2*2 + p)*2 + sub], qfh[ks], &kh4[p][sub*2]);
#pragma unroll
                for (int p = 0; p < 2; p++)
#pragma unroll
                    for (int sub = 0; sub < 2; sub++)
                        mma_f16(s[(nj2*2 + p)*2 + sub], qfl[ks], &kh4[p][sub*2]);
            }

        // ---- causal mask (scores already scaled via Q)
        if (k0 + 63 > q0 + wid * 16) {
#pragma unroll
            for (int j = 0; j < 8; j++)
#pragma unroll
                for (int c = 0; c < 4; c++) {
                    int key = k0 + j * 8 + 2 * (lane & 3) + (c & 1);
                    int row = qrow0 + ((c & 2) ? 8 : 0);
                    if (key > row) s[j][c] = -INFINITY;
                }
        }

        // ---- row max (rows r0 = regs 0,1; r0+8 = regs 2,3)
        float tm0 = -INFINITY, tm1 = -INFINITY;
#pragma unroll
        for (int j = 0; j < 8; j++) {
            tm0 = fmaxf(tm0, fmaxf(s[j][0], s[j][1]));
            tm1 = fmaxf(tm1, fmaxf(s[j][2], s[j][3]));
        }
        tm0 = fmaxf(tm0, __shfl_xor_sync(0xffffffffu, tm0, 1));
        tm0 = fmaxf(tm0, __shfl_xor_sync(0xffffffffu, tm0, 2));
        tm1 = fmaxf(tm1, __shfl_xor_sync(0xffffffffu, tm1, 1));
        tm1 = fmaxf(tm1, __shfl_xor_sync(0xffffffffu, tm1, 2));

        float mn0 = fmaxf(m0r, tm0), mn1 = fmaxf(m1r, tm1);
        float c0 = __expf(m0r - mn0), c1 = __expf(m1r - mn1);
        m0r = mn0; m1r = mn1;

        // ---- exp, pack P hi-only A-fragments, row sums
        float rs0 = 0.f, rs1 = 0.f;
        uint32_t ph[4][4];
#pragma unroll
        for (int j = 0; j < 4; j++) {
            float p[2][4];   // [ntile 2j / 2j+1][reg]
#pragma unroll
            for (int e = 0; e < 2; e++) {
                int nj = 2 * j + e;
                p[e][0] = __expf(s[nj][0] - mn0);
                p[e][1] = __expf(s[nj][1] - mn0);
                p[e][2] = __expf(s[nj][2] - mn1);
                p[e][3] = __expf(s[nj][3] - mn1);
                rs0 += p[e][0] + p[e][1];
                rs1 += p[e][2] + p[e][3];
            }
#pragma unroll
            for (int e = 0; e < 2; e++)
#pragma unroll
                for (int half = 0; half < 2; half++) {
                    __half2 hv;
                    hv.x = __float2half(p[e][half * 2 + 0]);
                    hv.y = __float2half(p[e][half * 2 + 1]);
                    ph[j][e * 2 + half] = *(uint32_t*)&hv;
                }
        }
        rs0 += __shfl_xor_sync(0xffffffffu, rs0, 1);
        rs0 += __shfl_xor_sync(0xffffffffu, rs0, 2);
        rs1 += __shfl_xor_sync(0xffffffffu, rs1, 1);
        rs1 += __shfl_xor_sync(0xffffffffu, rs1, 2);
        l0 = l0 * c0 + rs0;
        l1 = l1 * c1 + rs1;

        // ---- rescale O
#pragma unroll
        for (int j = 0; j < 8; j++) {
            o[j][0] *= c0; o[j][1] *= c0;
            o[j][2] *= c1; o[j][3] *= c1;
        }

        // ---- O += P V (1-term, term-major over vjp pairs), V via ldmatrix.trans
#pragma unroll
        for (int kt = 0; kt < 4; kt++)
#pragma unroll
            for (int vj2 = 0; vj2 < 2; vj2++) {
                uint32_t vh4[2][4];
#pragma unroll
                for (int p = 0; p < 2; p++) {
                    int vjp = vj2 * 2 + p;
                    int vrow = kt * 16 + vRowSel;
                    int vcol = vjp * 16 + vColSel;
                    ldsm_x4_t(vh4[p], smem_to_u32(sVh + vrow * APAD + vcol));
                }
#pragma unroll
                for (int p = 0; p < 2; p++)
#pragma unroll
                    for (int sub = 0; sub < 2; sub++)
                        mma_f16(o[(vj2*2 + p)*2 + sub], ph[kt], &vh4[p][sub*2]);
            }
        __syncthreads();   // stage consumed before refill in next iteration
    }

    // ---- epilogue: normalize, hi-only store to g_Ath
    float inv0 = 1.f / l0, inv1 = 1.f / l1;
    const int b = bh >> 4, h = bh & 15;
    const int s0 = q0 + wid * 16 + (lane >> 2);
#pragma unroll
    for (int nj = 0; nj < 8; nj++) {
        int col = h * 64 + nj * 8 + 2 * (lane & 3);
        size_t off0 = ((size_t)(b * 2048 + s0)) * 1024 + col;
        size_t off1 = ((size_t)(b * 2048 + s0 + 8)) * 1024 + col;
        __half2 h0, h1;
        h0.x = __float2half(o[nj][0] * inv0);
        h0.y = __float2half(o[nj][1] * inv0);
        h1.x = __float2half(o[nj][2] * inv1);
        h1.y = __float2half(o[nj][3] * inv1);
        *(__half2*)(g_Ath + off0) = h0;
        *(__half2*)(g_Ath + off1) = h1;
    }
}

// ---------------------------------------------------------------------------
extern "C" void kernel_launch(void* const* d_in, const int* in_sizes, int n_in,
                              void* d_out, int out_size)
{
    const float* x  = (const float*)d_in[0];
    const float* WQ = (const float*)d_in[1];
    const float* WK = (const float*)d_in[2];
    const float* WV = (const float*)d_in[3];
    const float* WO = (const float*)d_in[4];
    const int*  pos = (const int*)d_in[5];
    float* out = (float*)d_out;

    cudaFuncSetAttribute(attn_mma, cudaFuncAttributeMaxDynamicSharedMemorySize, ATTN_SMEM);
    cudaFuncSetAttribute(gemm_mma<0>, cudaFuncAttributeMaxDynamicSharedMemorySize, GT_SMEM);
    cudaFuncSetAttribute(gemm_mma<1>, cudaFuncAttributeMaxDynamicSharedMemorySize, GT_SMEM);

    // 1) RoPE tables
    rope_table_kernel<<<(SEQ*32 + 255)/256, 256>>>(pos);

    // 2) fp16 splits of X (hi+lo) and weights (hi only)
    split_x_kernel<<<8192, 256>>>(x);
    split_w_kernel<<<4096, 256>>>(WQ, WK, WV, WO);

    // 3) Fused QKV projection + RoPE; Q 2-term -> hi+lo (x1/8), K/V 1-term -> hi
    gemm_mma<0><<<dim3(24, 64), 256, GT_SMEM>>>(nullptr);

    // 4) Causal flash attention (S 2-term, PV 1-term, 2 CTAs/SM); writes g_Ath
    attn_mma<<<dim3(SEQ/128, BQ*NH), 256, ATTN_SMEM>>>();

    // 5) Output projection (1-term)
    gemm_mma<1><<<dim3(8, 64), 256, GT_SMEM>>>(out);
}

// round 17
// speedup vs baseline: 1.0668x; 1.0475x over previous
#include <cuda_runtime.h>
#include <cuda_fp16.h>
#include <math.h>
#include <stdint.h>

// Problem constants
#define BQ   4
#define SEQ  2048
#define DM   1024
#define NH   16
#define DKH  64
#define MTOT (BQ*SEQ)   // 8192

// ---------------------------------------------------------------------------
// Scratch (device globals: allocation-free)
// fp16 mixed-precision scheme (calibrated: sigma ~1.9e-4 per rounding source):
//   X: hi+lo.  Q projection: 2-term (feeds exponentiated scores).
//   K/V projections: 1-term (outputs rounded to fp16 anyway).
//   S = (Qh+Ql)@Kh: 2-term.  PV: 1-term.  Out-proj: 1-term.
// ---------------------------------------------------------------------------
__device__ float g_cos[SEQ*32];
__device__ float g_sin[SEQ*32];

__device__ __half g_Xh[(size_t)MTOT*DM];
__device__ __half g_Xl[(size_t)MTOT*DM];
__device__ __half g_Wh[(size_t)4096*DM];   // rows: WQ(0) WK(1024) WV(2048) WO(3072), hi only
__device__ __half g_Ath[(size_t)MTOT*DM];  // attention out, hi only (A-operand of out-proj)

// Q hi+lo (A-operand of S); K,V hi only (B-operands). [b,h,s,d]; Q pre-scaled 1/8.
__device__ __half g_Qh[(size_t)BQ*NH*SEQ*DKH];
__device__ __half g_Ql[(size_t)BQ*NH*SEQ*DKH];
__device__ __half g_Kh[(size_t)BQ*NH*SEQ*DKH];
__device__ __half g_Vh[(size_t)BQ*NH*SEQ*DKH];

// ---------------------------------------------------------------------------
// PTX helpers — portable (non-'a') instructions only.
// ---------------------------------------------------------------------------
__device__ __forceinline__ uint32_t smem_to_u32(const void* smem_ptr) {
    uint32_t addr;
    asm("{ .reg .u64 tmp; cvta.to.shared.u64 tmp, %1; cvt.u32.u64 %0, tmp; }"
        : "=r"(addr) : "l"(smem_ptr));
    return addr;
}

__device__ __forceinline__ void ldsm_x4(uint32_t* r, uint32_t addr) {
    asm volatile("ldmatrix.sync.aligned.m8n8.x4.shared.b16 {%0,%1,%2,%3}, [%4];"
        : "=r"(r[0]), "=r"(r[1]), "=r"(r[2]), "=r"(r[3]) : "r"(addr));
}
__device__ __forceinline__ void ldsm_x4_t(uint32_t* r, uint32_t addr) {
    asm volatile("ldmatrix.sync.aligned.m8n8.x4.trans.shared.b16 {%0,%1,%2,%3}, [%4];"
        : "=r"(r[0]), "=r"(r[1]), "=r"(r[2]), "=r"(r[3]) : "r"(addr));
}

__device__ __forceinline__ void mma_f16(float* d, const uint32_t* a, const uint32_t* b) {
    asm volatile(
        "mma.sync.aligned.m16n8k16.row.col.f32.f16.f16.f32 "
        "{%0,%1,%2,%3}, {%4,%5,%6,%7}, {%8,%9}, {%0,%1,%2,%3};"
        : "+f"(d[0]), "+f"(d[1]), "+f"(d[2]), "+f"(d[3])
        : "r"(a[0]), "r"(a[1]), "r"(a[2]), "r"(a[3]), "r"(b[0]), "r"(b[1]));
}

__device__ __forceinline__ void cp16(void* smem_dst, const void* gsrc) {
    uint32_t d = smem_to_u32(smem_dst);
    asm volatile("cp.async.cg.shared.global [%0], [%1], 16;" :: "r"(d), "l"(gsrc));
}
#define CP_COMMIT() asm volatile("cp.async.commit_group;" ::: "memory")
#define CP_WAIT0()  asm volatile("cp.async.wait_group 0;" ::: "memory")

// split fp32 pair -> fp16 hi/lo arrays (4B vectorized stores)
__device__ __forceinline__ void store_split2(__half* hp, __half* lp,
                                             size_t off, float a, float b)
{
    __half2 hv;
    hv.x = __float2half(a);
    hv.y = __float2half(b);
    __half2 lv;
    lv.x = __float2half(a - __half2float(hv.x));
    lv.y = __float2half(b - __half2float(hv.y));
    *(__half2*)(hp + off) = hv;
    *(__half2*)(lp + off) = lv;
}

// ---------------------------------------------------------------------------
// RoPE tables
// ---------------------------------------------------------------------------
__global__ void rope_table_kernel(const int* __restrict__ pos)
{
    int idx = blockIdx.x * blockDim.x + threadIdx.x;
    if (idx >= SEQ*32) return;
    int s = idx >> 5;
    int p = idx & 31;
    int position = pos[s];
    double freq = pow(10000.0, -(double)(2*p) / 64.0);
    float ang = (float)position * (float)freq;   // fp32 multiply like the ref
    g_cos[idx] = (float)cos((double)ang);
    g_sin[idx] = (float)sin((double)ang);
}

// ---------------------------------------------------------------------------
// fp32 -> fp16 splits
// ---------------------------------------------------------------------------
__device__ __forceinline__ void split1(float v, __half& h, __half& l)
{
    h = __float2half(v);
    l = __float2half(v - __half2float(h));
}

union Pack4 { __half b[4]; uint2 u; };

__global__ void split_x_kernel(const float* __restrict__ in)   // 8M elems, hi+lo
{
    size_t i = blockIdx.x * (size_t)blockDim.x + threadIdx.x;
    float4 v = ((const float4*)in)[i];
    Pack4 uh, ul;
    split1(v.x, uh.b[0], ul.b[0]);
    split1(v.y, uh.b[1], ul.b[1]);
    split1(v.z, uh.b[2], ul.b[2]);
    split1(v.w, uh.b[3], ul.b[3]);
    ((uint2*)g_Xh)[i] = uh.u;
    ((uint2*)g_Xl)[i] = ul.u;
}

// all four weight matrices, HI ONLY: grid 4096, matrix = blockIdx.x>>10
__global__ void split_w_kernel(const float* __restrict__ w0, const float* __restrict__ w1,
                               const float* __restrict__ w2, const float* __restrict__ w3)
{
    int mat = blockIdx.x >> 10;
    const float* in = (mat == 0) ? w0 : (mat == 1) ? w1 : (mat == 2) ? w2 : w3;
    size_t li = ((size_t)(blockIdx.x & 1023)) * blockDim.x + threadIdx.x;
    float4 v = ((const float4*)in)[li];
    Pack4 uh;
    uh.b[0] = __float2half(v.x);
    uh.b[1] = __float2half(v.y);
    uh.b[2] = __float2half(v.z);
    uh.b[3] = __float2half(v.w);
    size_t o = (size_t)mat * 262144 + li;    // 1024*1024/4 per matrix
    ((uint2*)g_Wh)[o] = uh.u;
}

// ---------------------------------------------------------------------------
// fp16 GEMM on mma.sync: C = Ah@Bh (+ Al@Bh only for Q-projection blocks).
// BK=64 (16 chunks — halves per-chunk barrier/wait fixed costs vs BK=32),
// 2-stage cp.async ring, issue-after-barrier, TWO CTAs per SM
// (2 x 110592 = 221184 <= 228KB carveout), term-major order.
//   Block 128x128, 8 warps (4m x 2n), warp tile 32x64.
// MODE 0: A = x-split, W rows [0,3072); epilogue RoPE (+1/8 for Q);
//         Q blocks (n0<1024): 2-term, hi+lo store. K/V blocks: 1-term, hi.
// MODE 1: A = g_Ath, W rows [3072,4096); 1-term; fp32 d_out.
// ---------------------------------------------------------------------------
#define GPAD 72                     // smem row stride in halves (144 bytes)
#define GT_TILE  (128*GPAD*2)       // 18432 B per tile (128 rows x 128B payload)
#define GT_STAGE (3*GT_TILE)        // 55296 B
#define GT_SMEM  (2*GT_STAGE)       // 110592 B

template<int MODE>
__global__ __launch_bounds__(256, 2)
void gemm_mma(float* __restrict__ Cout)
{
    extern __shared__ __align__(16) char gsm[];

    const int tid  = threadIdx.x;
    const int wid  = tid >> 5;
    const int lane = tid & 31;
    const int m0 = blockIdx.y * 128;
    const int n0 = blockIdx.x * 128;
    const int brow = (MODE == 0) ? n0 : (3072 + n0);
    const bool useAl = (MODE == 0) && (n0 < 1024);   // 2-term only for Q blocks

    const __half* Ah = (MODE == 0) ? g_Xh : g_Ath;
    const __half* Al = g_Xl;                          // only read when useAl

    const int warp_m0 = (wid & 3) * 32;
    const int warp_n0 = (wid >> 2) * 64;

    const uint32_t aRow = warp_m0 + (lane & 15);
    const uint32_t aCol = (lane >> 4) * 8;
    const uint32_t aOff = (aRow * GPAD + aCol) * 2;
    const uint32_t nRow = (lane & 7) | ((lane & 16) >> 1);
    const uint32_t kCol = ((lane >> 3) & 1) * 8;
    const uint32_t bOff = ((warp_n0 + nRow) * GPAD + kCol) * 2;

    // load addressing: 1024 16B-units per tile (128 rows x 8 segs), 4 per thread
    const int ldRow0  = tid >> 3;           // 0..31 (+32 per u)
    const int ldSegb  = (tid & 7) * 16;

    // issue cp.async loads of chunk ch (128B of k) into stage ch&1
    auto issueG = [&](int ch) {
        char* st = gsm + (ch & 1) * GT_STAGE;
        const int k0b = ch * 128;
#pragma unroll
        for (int u = 0; u < 4; u++) {
            int row = ldRow0 + u * 32;
            uint32_t so = (uint32_t)(row * (GPAD*2) + ldSegb);
            size_t gA = (size_t)(m0 + row) * 2048 + k0b + ldSegb;
            size_t gB = (size_t)(brow + row) * 2048 + k0b + ldSegb;
            cp16(st + 0*GT_TILE + so, (const char*)Ah   + gA);
            if (useAl)
                cp16(st + 1*GT_TILE + so, (const char*)Al + gA);
            cp16(st + 2*GT_TILE + so, (const char*)g_Wh + gB);
        }
        CP_COMMIT();
    };

    float acc[2][8][4];
#pragma unroll
    for (int i = 0; i < 2; i++)
#pragma unroll
        for (int j = 0; j < 8; j++)
#pragma unroll
            for (int c = 0; c < 4; c++) acc[i][j][c] = 0.f;

    issueG(0);

    for (int ch = 0; ch < 16; ch++) {
        CP_WAIT0();
        __syncthreads();
        if (ch + 1 < 16) issueG(ch + 1);

        const uint32_t stb = smem_to_u32(gsm + (ch & 1) * GT_STAGE);
        const uint32_t bAh = stb + 0*GT_TILE;
        const uint32_t bAl = stb + 1*GT_TILE;
        const uint32_t bBh = stb + 2*GT_TILE;

#pragma unroll
        for (int ks = 0; ks < 4; ks++) {
            const uint32_t kb = ks * 32;    // 16 halves per k-step
            uint32_t ahf[2][4], alf[2][4];
            uint32_t bh4[4][4];
#pragma unroll
            for (int mi = 0; mi < 2; mi++)
                ldsm_x4(ahf[mi], bAh + aOff + mi * (16*GPAD*2) + kb);
            if (useAl) {
#pragma unroll
                for (int mi = 0; mi < 2; mi++)
                    ldsm_x4(alf[mi], bAl + aOff + mi * (16*GPAD*2) + kb);
            }
#pragma unroll
            for (int nj = 0; nj < 4; nj++)
                ldsm_x4(bh4[nj], bBh + bOff + nj * (16*GPAD*2) + kb);
            // term-major mma stream (hi term; then lo term when used)
#pragma unroll
            for (int nj = 0; nj < 4; nj++)
#pragma unroll
                for (int mi = 0; mi < 2; mi++)
#pragma unroll
                    for (int sub = 0; sub < 2; sub++)
                        mma_f16(acc[mi][nj*2 + sub], ahf[mi], &bh4[nj][sub*2]);
            if (useAl) {
#pragma unroll
                for (int nj = 0; nj < 4; nj++)
#pragma unroll
                    for (int mi = 0; mi < 2; mi++)
#pragma unroll
                        for (int sub = 0; sub < 2; sub++)
                            mma_f16(acc[mi][nj*2 + sub], alf[mi], &bh4[nj][sub*2]);
            }
        }
    }

    const int mrow0 = m0 + warp_m0 + (lane >> 2);
    const int ncol0 = n0 + warp_n0 + 2 * (lane & 3);

    if (MODE == 0) {
        const int sel = n0 >> 10;                       // 0:Q 1:K 2:V
        __half* hp = (sel == 0) ? g_Qh : (sel == 1) ? g_Kh : g_Vh;
        const float sc_q = (sel == 0) ? 0.125f : 1.0f;  // fold 1/sqrt(d_k) into Q
#pragma unroll
        for (int mi = 0; mi < 2; mi++)
#pragma unroll
            for (int nt = 0; nt < 8; nt++) {
                int ngl = ncol0 + nt * 8;
                int o = ngl & 1023;
                int h = o >> 6, d = o & 63;             // d even
#pragma unroll
                for (int dr = 0; dr < 2; dr++) {
                    int m = mrow0 + mi * 16 + dr * 8;
                    int b = m >> 11, s = m & 2047;
                    size_t di = ((size_t)(b * 16 + h) * 2048 + s) * 64 + d;
                    float e  = acc[mi][nt][dr * 2];
                    float od = acc[mi][nt][dr * 2 + 1];
                    if (sel < 2) {
                        float cs = g_cos[s * 32 + (d >> 1)];
                        float sn = g_sin[s * 32 + (d >> 1)];
                        float e2 = (e * cs - od * sn) * sc_q;
                        od = (e * sn + od * cs) * sc_q;
                        e = e2;
                    }
                    if (sel == 0) {
                        store_split2(g_Qh, g_Ql, di, e, od);   // Q: hi+lo
                    } else {
                        __half2 hv;                            // K/V: hi only
                        hv.x = __float2half(e);
                        hv.y = __float2half(od);
                        *(__half2*)(hp + di) = hv;
                    }
                }
            }
    } else {
#pragma unroll
        for (int mi = 0; mi < 2; mi++)
#pragma unroll
            for (int nt = 0; nt < 8; nt++) {
                int ngl = ncol0 + nt * 8;
#pragma unroll
                for (int dr = 0; dr < 2; dr++) {
                    int m = mrow0 + mi * 16 + dr * 8;
                    *(float2*)(Cout + (size_t)m * 1024 + ngl) =
                        make_float2(acc[mi][nt][dr * 2], acc[mi][nt][dr * 2 + 1]);
                }
            }
    }
}

// ---------------------------------------------------------------------------
// Causal flash attention: S = (Qh+Ql)@Kh (2-term); O = Ph@Vh (1-term).
// TWO CTAs per SM (measured win). Key tiles of 64, cp.async 2-stage.
// Q pre-scaled by 1/8. Epilogue stores hi-only attention output.
// ---------------------------------------------------------------------------
#define APAD 72                  // halves; 144B stride (conflict-free ldmatrix)
#define KV_STAGE_BYTES (2*64*APAD*2)   // 18432
#define ATTN_SMEM (2*KV_STAGE_BYTES)   // 36864

__global__ __launch_bounds__(256, 2)
void attn_mma()
{
    extern __shared__ __align__(16) char dsm[];

    const int tid  = threadIdx.x;
    const int wid  = tid >> 5;
    const int lane = tid & 31;
    const int bh = blockIdx.y;                       // b*16 + h
    const int qi = (int)gridDim.x - 1 - (int)blockIdx.x;  // heavy blocks first
    const int q0 = qi * 128;
    const size_t base = (size_t)bh * SEQ * DKH;      // element offset

    // ---- Load Q tile (128 x 64 halves, hi/lo) into stage area, frag to regs
    __half* sQh = (__half*)dsm;
    __half* sQl = (__half*)dsm + 128*APAD;           // 36864 B, fits
#pragma unroll
    for (int u = 0; u < 4; u++) {
        int unit = tid + u * 256;                    // 1024 units per array
        int row = unit >> 3, seg = (unit & 7) * 8;
        size_t g = base + (size_t)(q0 + row) * 64 + seg;
        *(uint4*)(sQh + row * APAD + seg) = *(const uint4*)(g_Qh + g);
        *(uint4*)(sQl + row * APAD + seg) = *(const uint4*)(g_Ql + g);
    }
    __syncthreads();

    uint32_t qfh[4][4], qfl[4][4];
    {
        const int aRow = wid * 16 + (lane & 15);
        const int aCol = (lane >> 4) * 8;
#pragma unroll
        for (int kt = 0; kt < 4; kt++) {
            ldsm_x4(qfh[kt], smem_to_u32(sQh + aRow * APAD + kt * 16 + aCol));
            ldsm_x4(qfl[kt], smem_to_u32(sQl + aRow * APAD + kt * 16 + aCol));
        }
    }
    __syncthreads();   // Q consumed; smem stages free

    float o[8][4];
#pragma unroll
    for (int j = 0; j < 8; j++)
#pragma unroll
        for (int c = 0; c < 4; c++) o[j][c] = 0.f;
    float m0r = -INFINITY, m1r = -INFINITY;
    float l0 = 0.f, l1 = 0.f;

    const int ntiles = q0 / 64 + 2;

    // prefetch tile t into stage t&1 (Kh + Vh)
    auto issue = [&](int t) {
        const int k0 = t * 64;
        char* st = dsm + (t & 1) * KV_STAGE_BYTES;
        __half* dKh = (__half*)st;
        __half* dVh = (__half*)st + 64*APAD;
#pragma unroll
        for (int u = 0; u < 2; u++) {
            int unit = tid + u * 256;                // 512 units per array
            int row = unit >> 3, seg = (unit & 7) * 8;
            size_t g = base + (size_t)(k0 + row) * 64 + seg;
            int so = row * APAD + seg;
            cp16(dKh + so, g_Kh + g);
            cp16(dVh + so, g_Vh + g);
        }
        CP_COMMIT();
    };

    issue(0);

    const int bRow = (lane & 7) | ((lane & 16) >> 1);
    const int bK   = ((lane >> 3) & 1) * 8;
    const int vRowSel = (lane & 7) + ((lane >> 3) & 1) * 8;
    const int vColSel = ((lane >> 4) & 1) * 8;
    const int qrow0 = q0 + wid * 16 + (lane >> 2);

    for (int t = 0; t < ntiles; t++) {
        CP_WAIT0();
        __syncthreads();
        if (t + 1 < ntiles) issue(t + 1);

        const int k0 = t * 64;
        char* st = dsm + (t & 1) * KV_STAGE_BYTES;
        const __half* sKh = (const __half*)st;
        const __half* sVh = (const __half*)st + 64*APAD;

        // ---- S = Q K^T (2-term, term-major over njp pairs)
        float s[8][4];
#pragma unroll
        for (int j = 0; j < 8; j++)
#pragma unroll
            for (int c = 0; c < 4; c++) s[j][c] = 0.f;

#pragma unroll
        for (int ks = 0; ks < 4; ks++)
#pragma unroll
            for (int nj2 = 0; nj2 < 2; nj2++) {          // pairs of 16-col K tiles
                uint32_t kh4[2][4];
#pragma unroll
                for (int p = 0; p < 2; p++) {
                    int njp = nj2 * 2 + p;
                    ldsm_x4(kh4[p], smem_to_u32(sKh + (njp * 16 + bRow) * APAD + ks * 16 + bK));
                }
#pragma unroll
                for (int p = 0; p < 2; p++)
#pragma unroll
                    for (int sub = 0; sub < 2; sub++)
                        mma_f16(s[(nj2*2 + p)*2 + sub], qfh[ks], &kh4[p][sub*2]);
#pragma unroll
                for (int p = 0; p < 2; p++)
#pragma unroll
                    for (int sub = 0; sub < 2; sub++)
                        mma_f16(s[(nj2*2 + p)*2 + sub], qfl[ks], &kh4[p][sub*2]);
            }

        // ---- causal mask (scores already scaled via Q)
        if (k0 + 63 > q0 + wid * 16) {
#pragma unroll
            for (int j = 0; j < 8; j++)
#pragma unroll
                for (int c = 0; c < 4; c++) {
                    int key = k0 + j * 8 + 2 * (lane & 3) + (c & 1);
                    int row = qrow0 + ((c & 2) ? 8 : 0);
                    if (key > row) s[j][c] = -INFINITY;
                }
        }

        // ---- row max (rows r0 = regs 0,1; r0+8 = regs 2,3)
        float tm0 = -INFINITY, tm1 = -INFINITY;
#pragma unroll
        for (int j = 0; j < 8; j++) {
            tm0 = fmaxf(tm0, fmaxf(s[j][0], s[j][1]));
            tm1 = fmaxf(tm1, fmaxf(s[j][2], s[j][3]));
        }
        tm0 = fmaxf(tm0, __shfl_xor_sync(0xffffffffu, tm0, 1));
        tm0 = fmaxf(tm0, __shfl_xor_sync(0xffffffffu, tm0, 2));
        tm1 = fmaxf(tm1, __shfl_xor_sync(0xffffffffu, tm1, 1));
        tm1 = fmaxf(tm1, __shfl_xor_sync(0xffffffffu, tm1, 2));

        float mn0 = fmaxf(m0r, tm0), mn1 = fmaxf(m1r, tm1);
        float c0 = __expf(m0r - mn0), c1 = __expf(m1r - mn1);
        m0r = mn0; m1r = mn1;

        // ---- exp, pack P hi-only A-fragments, row sums
        float rs0 = 0.f, rs1 = 0.f;
        uint32_t ph[4][4];
#pragma unroll
        for (int j = 0; j < 4; j++) {
            float p[2][4];   // [ntile 2j / 2j+1][reg]
#pragma unroll
            for (int e = 0; e < 2; e++) {
                int nj = 2 * j + e;
                p[e][0] = __expf(s[nj][0] - mn0);
                p[e][1] = __expf(s[nj][1] - mn0);
                p[e][2] = __expf(s[nj][2] - mn1);
                p[e][3] = __expf(s[nj][3] - mn1);
                rs0 += p[e][0] + p[e][1];
                rs1 += p[e][2] + p[e][3];
            }
#pragma unroll
            for (int e = 0; e < 2; e++)
#pragma unroll
                for (int half = 0; half < 2; half++) {
                    __half2 hv;
                    hv.x = __float2half(p[e][half * 2 + 0]);
                    hv.y = __float2half(p[e][half * 2 + 1]);
                    ph[j][e * 2 + half] = *(uint32_t*)&hv;
                }
        }
        rs0 += __shfl_xor_sync(0xffffffffu, rs0, 1);
        rs0 += __shfl_xor_sync(0xffffffffu, rs0, 2);
        rs1 += __shfl_xor_sync(0xffffffffu, rs1, 1);
        rs1 += __shfl_xor_sync(0xffffffffu, rs1, 2);
        l0 = l0 * c0 + rs0;
        l1 = l1 * c1 + rs1;

        // ---- rescale O
#pragma unroll
        for (int j = 0; j < 8; j++) {
            o[j][0] *= c0; o[j][1] *= c0;
            o[j][2] *= c1; o[j][3] *= c1;
        }

        // ---- O += P V (1-term, term-major over vjp pairs), V via ldmatrix.trans
#pragma unroll
        for (int kt = 0; kt < 4; kt++)
#pragma unroll
            for (int vj2 = 0; vj2 < 2; vj2++) {
                uint32_t vh4[2][4];
#pragma unroll
                for (int p = 0; p < 2; p++) {
                    int vjp = vj2 * 2 + p;
                    int vrow = kt * 16 + vRowSel;
                    int vcol = vjp * 16 + vColSel;
                    ldsm_x4_t(vh4[p], smem_to_u32(sVh + vrow * APAD + vcol));
                }
#pragma unroll
                for (int p = 0; p < 2; p++)
#pragma unroll
                    for (int sub = 0; sub < 2; sub++)
                        mma_f16(o[(vj2*2 + p)*2 + sub], ph[kt], &vh4[p][sub*2]);
            }
        __syncthreads();   // stage consumed before refill in next iteration
    }

    // ---- epilogue: normalize, hi-only store to g_Ath
    float inv0 = 1.f / l0, inv1 = 1.f / l1;
    const int b = bh >> 4, h = bh & 15;
    const int s0 = q0 + wid * 16 + (lane >> 2);
#pragma unroll
    for (int nj = 0; nj < 8; nj++) {
        int col = h * 64 + nj * 8 + 2 * (lane & 3);
        size_t off0 = ((size_t)(b * 2048 + s0)) * 1024 + col;
        size_t off1 = ((size_t)(b * 2048 + s0 + 8)) * 1024 + col;
        __half2 h0, h1;
        h0.x = __float2half(o[nj][0] * inv0);
        h0.y = __float2half(o[nj][1] * inv0);
        h1.x = __float2half(o[nj][2] * inv1);
        h1.y = __float2half(o[nj][3] * inv1);
        *(__half2*)(g_Ath + off0) = h0;
        *(__half2*)(g_Ath + off1) = h1;
    }
}

// ---------------------------------------------------------------------------
extern "C" void kernel_launch(void* const* d_in, const int* in_sizes, int n_in,
                              void* d_out, int out_size)
{
    const float* x  = (const float*)d_in[0];
    const float* WQ = (const float*)d_in[1];
    const float* WK = (const float*)d_in[2];
    const float* WV = (const float*)d_in[3];
    const float* WO = (const float*)d_in[4];
    const int*  pos = (const int*)d_in[5];
    float* out = (float*)d_out;

    cudaFuncSetAttribute(attn_mma, cudaFuncAttributeMaxDynamicSharedMemorySize, ATTN_SMEM);
    cudaFuncSetAttribute(gemm_mma<0>, cudaFuncAttributeMaxDynamicSharedMemorySize, GT_SMEM);
    cudaFuncSetAttribute(gemm_mma<1>, cudaFuncAttributeMaxDynamicSharedMemorySize, GT_SMEM);

    // 1) RoPE tables
    rope_table_kernel<<<(SEQ*32 + 255)/256, 256>>>(pos);

    // 2) fp16 splits of X (hi+lo) and weights (hi only)
    split_x_kernel<<<8192, 256>>>(x);
    split_w_kernel<<<4096, 256>>>(WQ, WK, WV, WO);

    // 3) Fused QKV projection + RoPE; Q 2-term -> hi+lo (x1/8), K/V 1-term -> hi
    gemm_mma<0><<<dim3(24, 64), 256, GT_SMEM>>>(nullptr);

    // 4) Causal flash attention (S 2-term, PV 1-term, 2 CTAs/SM); writes g_Ath
    attn_mma<<<dim3(SEQ/128, BQ*NH), 256, ATTN_SMEM>>>();

    // 5) Output projection (1-term)
    gemm_mma<1><<<dim3(8, 64), 256, GT_SMEM>>>(out);
}